// round 1
// baseline (speedup 1.0000x reference)
#include <cuda_runtime.h>

// Problem constants
#define NQ     4
#define QDIM   16
#define QDEPTH 6
#define DFEAT  512   // input feature dim

// Folded quadratic-form matrices: out_j = s^T T_j s + b_post_j
__device__ float g_T[2][QDIM][QDIM];

__device__ __forceinline__ int perm_idx(int i, int c, int t) {
    int cbit = (i >> (3 - c)) & 1;
    return i ^ (cbit << (3 - t));
}

// One small block: build M (the fixed 16x16 circuit matrix from q_params),
// then T_j[k][l] = sum_i G[i][j] * M[i][k] * M[i][l],  G = Z_SIGNS @ W_post.
__global__ void qst_setup_kernel(const float* __restrict__ q_params,
                                 const float* __restrict__ W_post)
{
    __shared__ float sM[QDIM][QDIM];
    const int tid = threadIdx.x;

    if (tid < QDIM) {
        float v[QDIM];
        #pragma unroll
        for (int i = 0; i < QDIM; i++) v[i] = (i == tid) ? 1.0f : 0.0f;

        for (int k = 0; k < QDEPTH; k++) {
            // CNOT perms: (c=0,t=1), (c=2,t=3), (c=1,t=2)   new[i] = old[perm[i]]
            const int cs[3] = {0, 2, 1};
            const int ts[3] = {1, 3, 2};
            #pragma unroll
            for (int p = 0; p < 3; p++) {
                float tmp[QDIM];
                #pragma unroll
                for (int i = 0; i < QDIM; i++) tmp[i] = v[perm_idx(i, cs[p], ts[p])];
                #pragma unroll
                for (int i = 0; i < QDIM; i++) v[i] = tmp[i];
            }
            // RY layer with q_params[k*4 + w]
            for (int w = 0; w < NQ; w++) {
                float half = 0.5f * q_params[k * NQ + w];
                float sn, cn;
                sincosf(half, &sn, &cn);
                int mask = 1 << (3 - w);
                #pragma unroll
                for (int i = 0; i < QDIM; i++) {
                    if (i & mask) continue;
                    int jj = i | mask;
                    float a = v[i], b = v[jj];
                    v[i]  = cn * a - sn * b;
                    v[jj] = sn * a + cn * b;
                }
            }
        }
        #pragma unroll
        for (int i = 0; i < QDIM; i++) sM[i][tid] = v[i];
    }
    __syncthreads();

    // 512 threads: (j, k, l)
    const int j = tid >> 8;
    const int k = (tid >> 4) & 15;
    const int l = tid & 15;
    float acc = 0.0f;
    #pragma unroll
    for (int i = 0; i < QDIM; i++) {
        float g = 0.0f;
        #pragma unroll
        for (int w = 0; w < NQ; w++) {
            float z = 1.0f - 2.0f * (float)((i >> (3 - w)) & 1);
            g += z * W_post[w * 2 + j];
        }
        acc += g * sM[i][k] * sM[i][l];
    }
    g_T[j][k][l] = acc;
}

// Main fused kernel: one warp per row (grid-stride).
// Lane layout: dot-product lanes read 4 coalesced float4 chunks of the row;
// W_pre is register-resident (64 regs/lane). Epilogue: lane (j*16+k) owns
// T_j row k and computes v_k = sum_l T[k][l] s_l via warp shuffles.
__global__ __launch_bounds__(256, 2)
void qst_main_kernel(const float4* __restrict__ X,      // [B, 128] float4
                     const float4* __restrict__ Wpre,   // [512] float4 rows
                     const float*  __restrict__ b_pre,  // [4]
                     const float*  __restrict__ b_post, // [2]
                     float* __restrict__ out,           // [B, 2]
                     int B)
{
    const int lane  = threadIdx.x & 31;
    const int gwarp = (int)((blockIdx.x * blockDim.x + threadIdx.x) >> 5);
    const int nwarp = (int)((gridDim.x * blockDim.x) >> 5);

    // Register-resident W_pre slice: lane uses feature rows i*128 + lane*4 + c
    float4 W[16];
    #pragma unroll
    for (int i = 0; i < 4; i++)
        #pragma unroll
        for (int c = 0; c < 4; c++)
            W[i * 4 + c] = Wpre[i * 128 + lane * 4 + c];

    const int j = lane >> 4;     // which output (0/1)
    const int k = lane & 15;     // which state index
    float Trow[16];
    #pragma unroll
    for (int l = 0; l < 16; l++) Trow[l] = g_T[j][k][l];

    const float bp0 = b_pre[0], bp1 = b_pre[1], bp2 = b_pre[2], bp3 = b_pre[3];
    const float bpost = b_post[j];
    const float PI4 = 0.78539816339744831f;   // pi/4
    const float IS2 = 0.70710678118654752f;   // 1/sqrt(2)

    const int b0 = (k >> 3) & 1, b1 = (k >> 2) & 1, b2 = (k >> 1) & 1, b3 = k & 1;

    for (int row = gwarp; row < B; row += nwarp) {
        const float4* xr = X + (size_t)row * 128;

        float a0 = 0.f, a1 = 0.f, a2 = 0.f, a3 = 0.f;
        #pragma unroll
        for (int i = 0; i < 4; i++) {
            float4 x  = xr[i * 32 + lane];         // coalesced 512B per warp
            float4 w0 = W[i * 4 + 0], w1 = W[i * 4 + 1];
            float4 w2 = W[i * 4 + 2], w3 = W[i * 4 + 3];
            a0 = fmaf(x.x, w0.x, fmaf(x.y, w1.x, fmaf(x.z, w2.x, fmaf(x.w, w3.x, a0))));
            a1 = fmaf(x.x, w0.y, fmaf(x.y, w1.y, fmaf(x.z, w2.y, fmaf(x.w, w3.y, a1))));
            a2 = fmaf(x.x, w0.z, fmaf(x.y, w1.z, fmaf(x.z, w2.z, fmaf(x.w, w3.z, a2))));
            a3 = fmaf(x.x, w0.w, fmaf(x.y, w1.w, fmaf(x.z, w2.w, fmaf(x.w, w3.w, a3))));
        }
        // full-warp butterfly reduce of 4 partial dots
        #pragma unroll
        for (int off = 16; off; off >>= 1) {
            a0 += __shfl_xor_sync(0xffffffffu, a0, off);
            a1 += __shfl_xor_sync(0xffffffffu, a1, off);
            a2 += __shfl_xor_sync(0xffffffffu, a2, off);
            a3 += __shfl_xor_sync(0xffffffffu, a3, off);
        }

        float pre[4] = { a0 + bp0, a1 + bp1, a2 + bp2, a3 + bp3 };

        // per-qubit rotation vectors u_w = ((c-s)/sqrt2, (c+s)/sqrt2),
        // angle = tanh(pre)*pi/4  (exp-based tanh, ~1e-6 accurate)
        float u[4][2];
        #pragma unroll
        for (int w = 0; w < 4; w++) {
            float e = __expf(2.0f * pre[w]);
            float t = 1.0f - __fdividef(2.0f, e + 1.0f);
            float sn, cn;
            __sincosf(t * PI4, &sn, &cn);
            u[w][0] = (cn - sn) * IS2;
            u[w][1] = (cn + sn) * IS2;
        }

        // s_k = product of selected per-qubit components (rank-1 state)
        float s = u[0][b0] * u[1][b1] * u[2][b2] * u[3][b3];

        // v_k = sum_l T_j[k][l] * s_l  (s_l lives on lane l)
        float v = 0.0f;
        #pragma unroll
        for (int l = 0; l < 16; l++)
            v = fmaf(Trow[l], __shfl_sync(0xffffffffu, s, l), v);

        // y_j = sum_k s_k * v_k over each 16-lane group
        float p = v * s;
        p += __shfl_xor_sync(0xffffffffu, p, 1);
        p += __shfl_xor_sync(0xffffffffu, p, 2);
        p += __shfl_xor_sync(0xffffffffu, p, 4);
        p += __shfl_xor_sync(0xffffffffu, p, 8);

        if (k == 0) out[row * 2 + j] = p + bpost;
    }
}

extern "C" void kernel_launch(void* const* d_in, const int* in_sizes, int n_in,
                              void* d_out, int out_size)
{
    const float* X     = (const float*)d_in[0];  // [B, 512]
    const float* Wpre  = (const float*)d_in[1];  // [512, 4]
    const float* bpre  = (const float*)d_in[2];  // [4]
    const float* qp    = (const float*)d_in[3];  // [24]
    const float* Wpost = (const float*)d_in[4];  // [4, 2]
    const float* bpost = (const float*)d_in[5];  // [2]
    int B = in_sizes[0] / DFEAT;

    qst_setup_kernel<<<1, 512>>>(qp, Wpost);
    qst_main_kernel<<<1184, 256>>>((const float4*)X, (const float4*)Wpre,
                                   bpre, bpost, (float*)d_out, B);
}

// round 3
// speedup vs baseline: 1.4617x; 1.4617x over previous
#include <cuda_runtime.h>

#define NQ     4
#define QDIM   16
#define QDEPTH 6
#define DFEAT  512
#define ROWS   256            // rows per block
#define NITER  32             // 512 feats / 16 per iter

// Folded circuit: amp = M @ s (rank-1 encoded state),  out_j = sum_i G[i][j] * amp_i^2
__device__ float g_M[QDIM * QDIM];
__device__ float g_G[QDIM * 2];

__device__ __forceinline__ int perm_idx(int i, int c, int t) {
    int cbit = (i >> (3 - c)) & 1;
    return i ^ (cbit << (3 - t));
}

__global__ void qst_setup_kernel(const float* __restrict__ q_params,
                                 const float* __restrict__ W_post)
{
    __shared__ float sM[QDIM][QDIM];
    const int tid = threadIdx.x;

    if (tid < QDIM) {
        float v[QDIM];
        #pragma unroll
        for (int i = 0; i < QDIM; i++) v[i] = (i == tid) ? 1.0f : 0.0f;

        for (int k = 0; k < QDEPTH; k++) {
            const int cs[3] = {0, 2, 1};
            const int ts[3] = {1, 3, 2};
            #pragma unroll
            for (int p = 0; p < 3; p++) {
                float tmp[QDIM];
                #pragma unroll
                for (int i = 0; i < QDIM; i++) tmp[i] = v[perm_idx(i, cs[p], ts[p])];
                #pragma unroll
                for (int i = 0; i < QDIM; i++) v[i] = tmp[i];
            }
            for (int w = 0; w < NQ; w++) {
                float half = 0.5f * q_params[k * NQ + w];
                float sn, cn;
                sincosf(half, &sn, &cn);
                int mask = 1 << (3 - w);
                #pragma unroll
                for (int i = 0; i < QDIM; i++) {
                    if (i & mask) continue;
                    int jj = i | mask;
                    float a = v[i], b = v[jj];
                    v[i]  = cn * a - sn * b;
                    v[jj] = sn * a + cn * b;
                }
            }
        }
        #pragma unroll
        for (int i = 0; i < QDIM; i++) sM[i][tid] = v[i];
    }
    __syncthreads();

    if (tid < QDIM * QDIM)
        g_M[tid] = sM[tid >> 4][tid & 15];

    if (tid < QDIM * 2) {
        int i = tid >> 1, j = tid & 1;
        float g = 0.0f;
        #pragma unroll
        for (int w = 0; w < NQ; w++) {
            float z = 1.0f - 2.0f * (float)((i >> (3 - w)) & 1);
            g += z * W_post[w * 2 + j];
        }
        g_G[tid] = g;
    }
}

// Main kernel: multiply-at-load. Thread (r=t>>2, c=t&3) owns rows r+64q (q=0..3),
// float4-columns c+4*it. No smem staging of X, no barriers in main loop.
__global__ __launch_bounds__(256, 4)
void qst_main_kernel(const float4* __restrict__ X,     // [B,128] float4
                     const float4* __restrict__ Wpre,  // [512] float4 (4 outs per feat)
                     const float*  __restrict__ b_pre,
                     const float*  __restrict__ b_post,
                     float2* __restrict__ out,         // [B]
                     int B)
{
    // W_pre, padded stride-5 per 4-float4 group: p = u + (u>>2) -> conflict-free LDS
    __shared__ float4 ws[DFEAT + DFEAT / 4];   // 640 float4 = 10 KB
    __shared__ float  sM[QDIM * QDIM];
    __shared__ float  sG[QDIM * 2];

    const int t = threadIdx.x;

    {
        int f0 = t, f1 = t + 256;
        ws[f0 + (f0 >> 2)] = Wpre[f0];
        ws[f1 + (f1 >> 2)] = Wpre[f1];
        sM[t & 255] = g_M[t & 255];
        if (t < QDIM * 2) sG[t] = g_G[t];
    }
    __syncthreads();

    const int c    = t & 3;
    const int r    = t >> 2;            // 0..63
    const int row0 = blockIdx.x << 8;

    // clamped row base pointers (element index fits int: 131072*128 < 2^31)
    const float4* xp0 = X + (min(row0 + r,       B - 1) * 128 + c);
    const float4* xp1 = X + (min(row0 + r +  64, B - 1) * 128 + c);
    const float4* xp2 = X + (min(row0 + r + 128, B - 1) * 128 + c);
    const float4* xp3 = X + (min(row0 + r + 192, B - 1) * 128 + c);

    float acc[16];
    #pragma unroll
    for (int i = 0; i < 16; i++) acc[i] = 0.0f;

    const int wc = c * 5;   // padded offset of this lane's W group within an iter

    #pragma unroll 4
    for (int it = 0; it < NITER; it++) {
        const float4* wp = ws + it * 20 + wc;
        float4 wA = wp[0], wB = wp[1], wC = wp[2], wD = wp[3];

        float4 x0 = xp0[it * 4];
        float4 x1 = xp1[it * 4];
        float4 x2 = xp2[it * 4];
        float4 x3 = xp3[it * 4];

        #pragma unroll
        for (int q = 0; q < 4; q++) {
            float4 x = (q == 0) ? x0 : (q == 1) ? x1 : (q == 2) ? x2 : x3;
            acc[q*4+0] = fmaf(x.x, wA.x, fmaf(x.y, wB.x, fmaf(x.z, wC.x, fmaf(x.w, wD.x, acc[q*4+0]))));
            acc[q*4+1] = fmaf(x.x, wA.y, fmaf(x.y, wB.y, fmaf(x.z, wC.y, fmaf(x.w, wD.y, acc[q*4+1]))));
            acc[q*4+2] = fmaf(x.x, wA.z, fmaf(x.y, wB.z, fmaf(x.z, wC.z, fmaf(x.w, wD.z, acc[q*4+2]))));
            acc[q*4+3] = fmaf(x.x, wA.w, fmaf(x.y, wB.w, fmaf(x.z, wC.w, fmaf(x.w, wD.w, acc[q*4+3]))));
        }
    }

    // Reduce over the 4-lane c-quad (once per block)
    #pragma unroll
    for (int i = 0; i < 16; i++) {
        acc[i] += __shfl_xor_sync(0xffffffffu, acc[i], 1);
        acc[i] += __shfl_xor_sync(0xffffffffu, acc[i], 2);
    }

    // Redistribute: lane t owns row row0 + (t>>2) + 64*(t&3), taking q_sel = t&3
    const int q_sel = t & 3;
    const int row   = row0 + (t >> 2) + 64 * q_sel;

    float pre[4];
    #pragma unroll
    for (int o = 0; o < 4; o++) {
        float v = acc[o];
        v = (q_sel == 1) ? acc[4 + o]  : v;
        v = (q_sel == 2) ? acc[8 + o]  : v;
        v = (q_sel == 3) ? acc[12 + o] : v;
        pre[o] = v + b_pre[o];
    }

    // ---- folded-circuit epilogue (straight-line, per-thread) ----
    const float PI4 = 0.78539816339744831f;
    const float IS2 = 0.70710678118654752f;

    float u[4][2];
    #pragma unroll
    for (int w = 0; w < 4; w++) {
        float e  = __expf(2.0f * pre[w]);
        float th = 1.0f - __fdividef(2.0f, e + 1.0f);   // tanh(pre)
        float sn, cn;
        __sincosf(th * PI4, &sn, &cn);
        u[w][0] = (cn - sn) * IS2;
        u[w][1] = (cn + sn) * IS2;
    }

    float p01[4], p23[4];
    #pragma unroll
    for (int a = 0; a < 4; a++) {
        p01[a] = u[0][a >> 1] * u[1][a & 1];
        p23[a] = u[2][a >> 1] * u[3][a & 1];
    }
    float s[16];
    #pragma unroll
    for (int k = 0; k < 16; k++)
        s[k] = p01[k >> 2] * p23[k & 3];

    const float4* M4 = (const float4*)sM;   // uniform -> broadcast
    float o0 = 0.f, o1 = 0.f;
    #pragma unroll
    for (int i = 0; i < 16; i++) {
        float m = 0.f;
        #pragma unroll
        for (int k4 = 0; k4 < 4; k4++) {
            float4 mv = M4[i * 4 + k4];
            m = fmaf(mv.x, s[k4 * 4 + 0],
                fmaf(mv.y, s[k4 * 4 + 1],
                fmaf(mv.z, s[k4 * 4 + 2],
                fmaf(mv.w, s[k4 * 4 + 3], m))));
        }
        float mm = m * m;
        o0 = fmaf(sG[i * 2 + 0], mm, o0);
        o1 = fmaf(sG[i * 2 + 1], mm, o1);
    }

    if (row < B)
        out[row] = make_float2(o0 + b_post[0], o1 + b_post[1]);
}

extern "C" void kernel_launch(void* const* d_in, const int* in_sizes, int n_in,
                              void* d_out, int out_size)
{
    const float* X     = (const float*)d_in[0];  // [B, 512]
    const float* Wpre  = (const float*)d_in[1];  // [512, 4]
    const float* bpre  = (const float*)d_in[2];  // [4]
    const float* qp    = (const float*)d_in[3];  // [24]
    const float* Wpost = (const float*)d_in[4];  // [4, 2]
    const float* bpost = (const float*)d_in[5];  // [2]
    int B = in_sizes[0] / DFEAT;

    qst_setup_kernel<<<1, 512>>>(qp, Wpost);

    int nblk = (B + ROWS - 1) / ROWS;
    qst_main_kernel<<<nblk, 256>>>((const float4*)X, (const float4*)Wpre,
                                   bpre, bpost, (float2*)d_out, B);
}